// round 1
// baseline (speedup 1.0000x reference)
#include <cuda_runtime.h>
#include <math.h>

#define D_MODEL 1024
#define NHEAD   16
#define HEAD_DIM 64
#define BATCH   2
#define SEQ     2048
#define M_TOT   (BATCH*SEQ)          // 4096

// Scratch: Q/K/V in [B, H, L, S] layout (16 MB each)
__device__ float g_Q[BATCH*NHEAD*SEQ*HEAD_DIM];
__device__ float g_K[BATCH*NHEAD*SEQ*HEAD_DIM];
__device__ float g_V[BATCH*NHEAD*SEQ*HEAD_DIM];

// log2(10000)
#define LOG2_10K 13.287712379549449f

// ---------------------------------------------------------------------------
// Kernel 1: fused QKV GEMM + bias + RoPE (for Q,K), writes [B,H,L,S] scratch.
// C[m][n] = sum_k data[m][k] * W[k][n];  m = b*SEQ+l token row.
// BM=64, BN=64, BK=16, 256 threads, 4x4 micro-tile per thread.
// blockIdx.z selects matrix: 0=Q, 1=K, 2=V.
// ---------------------------------------------------------------------------
__global__ __launch_bounds__(256) void qkv_rope_kernel(
    const float* __restrict__ data, const float* __restrict__ temporal,
    const float* __restrict__ Wq, const float* __restrict__ bq,
    const float* __restrict__ Wk, const float* __restrict__ bk,
    const float* __restrict__ Wv, const float* __restrict__ bv)
{
    const int mat = blockIdx.z;
    const float* __restrict__ W    = (mat == 0) ? Wq : ((mat == 1) ? Wk : Wv);
    const float* __restrict__ bias = (mat == 0) ? bq : ((mat == 1) ? bk : bv);
    float* __restrict__ out        = (mat == 0) ? g_Q : ((mat == 1) ? g_K : g_V);

    __shared__ float As[16][65];   // [k][m], stride 65 -> conflict-free xposed stores
    __shared__ float Bs[16][64];   // [k][n]

    const int tid = threadIdx.x;
    const int tx = tid & 15;       // col group
    const int ty = tid >> 4;       // row group
    const int m0 = blockIdx.x * 64;
    const int n0 = blockIdx.y * 64;

    // A tile loader coords: 64 rows x 16 k, one float4 per thread
    const int lr = tid >> 2;             // 0..63
    const int lk = (tid & 3) * 4;        // 0,4,8,12
    // B tile loader coords: 16 k x 64 n, one float4 per thread
    const int bkr = tid >> 4;            // 0..15
    const int bnc = (tid & 15) * 4;      // 0..60

    float acc[4][4];
    #pragma unroll
    for (int i = 0; i < 4; i++)
        #pragma unroll
        for (int j = 0; j < 4; j++) acc[i][j] = 0.0f;

    for (int kk = 0; kk < D_MODEL; kk += 16) {
        float4 av = *(const float4*)(data + (size_t)(m0 + lr) * D_MODEL + kk + lk);
        float4 bvv = *(const float4*)(W + (size_t)(kk + bkr) * D_MODEL + n0 + bnc);
        As[lk + 0][lr] = av.x;
        As[lk + 1][lr] = av.y;
        As[lk + 2][lr] = av.z;
        As[lk + 3][lr] = av.w;
        *(float4*)&Bs[bkr][bnc] = bvv;
        __syncthreads();

        #pragma unroll
        for (int k = 0; k < 16; k++) {
            float a0 = As[k][ty * 4 + 0];
            float a1 = As[k][ty * 4 + 1];
            float a2 = As[k][ty * 4 + 2];
            float a3 = As[k][ty * 4 + 3];
            float4 b4 = *(const float4*)&Bs[k][tx * 4];
            acc[0][0] += a0 * b4.x; acc[0][1] += a0 * b4.y; acc[0][2] += a0 * b4.z; acc[0][3] += a0 * b4.w;
            acc[1][0] += a1 * b4.x; acc[1][1] += a1 * b4.y; acc[1][2] += a1 * b4.z; acc[1][3] += a1 * b4.w;
            acc[2][0] += a2 * b4.x; acc[2][1] += a2 * b4.y; acc[2][2] += a2 * b4.z; acc[2][3] += a2 * b4.w;
            acc[3][0] += a3 * b4.x; acc[3][1] += a3 * b4.y; acc[3][2] += a3 * b4.z; acc[3][3] += a3 * b4.w;
        }
        __syncthreads();
    }

    // Epilogue: bias (+RoPE for Q/K), store to [B,H,L,S].
    // All 4 cols of a thread live in one head (n0 is a multiple of 64).
    const int h = n0 >> 6;
    const int sbase = tx * 4;       // even -> RoPE pairs (sbase,sbase+1),(sbase+2,sbase+3)
    float b0 = bias[n0 + sbase + 0];
    float b1 = bias[n0 + sbase + 1];
    float b2 = bias[n0 + sbase + 2];
    float b3 = bias[n0 + sbase + 3];
    // freq uses the even member of each pair
    float f0 = exp2f(-(float)(sbase)     * (LOG2_10K / (float)HEAD_DIM));
    float f1 = exp2f(-(float)(sbase + 2) * (LOG2_10K / (float)HEAD_DIM));

    #pragma unroll
    for (int i = 0; i < 4; i++) {
        int r = m0 + ty * 4 + i;          // token row
        int b = r >> 11;                  // r / SEQ
        int l = r & (SEQ - 1);
        float c0 = acc[i][0] + b0;
        float c1 = acc[i][1] + b1;
        float c2 = acc[i][2] + b2;
        float c3 = acc[i][3] + b3;
        float4 v;
        if (mat < 2) {
            float t = temporal[r];
            float s0, cs0, s1, cs1;
            sincosf(t * f0, &s0, &cs0);
            sincosf(t * f1, &s1, &cs1);
            v.x = c0 * cs0 - c1 * s0;
            v.y = c1 * cs0 + c0 * s0;
            v.z = c2 * cs1 - c3 * s1;
            v.w = c3 * cs1 + c2 * s1;
        } else {
            v = make_float4(c0, c1, c2, c3);
        }
        size_t idx = (((size_t)(b * NHEAD + h)) * SEQ + l) * HEAD_DIM + sbase;
        *(float4*)(out + idx) = v;
    }
}

// ---------------------------------------------------------------------------
// Kernel 2: flash attention, fp32, 64x64 tiles, online softmax.
// grid(SEQ/64, NHEAD, BATCH), 256 threads (16x16), 4x4 micro-tile.
// Thread (ty,tx) owns rows {ty+16i}, cols {tx+16j}  (strided mapping ->
// conflict-free LDS.128 at row stride 68 floats).
// smem: Qs | KPs (K tile, then P tile) | Vs ; each 64*68 floats.
// ---------------------------------------------------------------------------
#define AT_STRIDE 68
#define AT_TILE   (64 * AT_STRIDE)
#define AT_SMEM_BYTES (3 * AT_TILE * (int)sizeof(float))

__global__ __launch_bounds__(256) void flash_attn_kernel(
    const float* __restrict__ mask, float* __restrict__ out)
{
    extern __shared__ float sm[];
    float* Qs  = sm;
    float* KPs = sm + AT_TILE;
    float* Vs  = sm + 2 * AT_TILE;

    const int tid = threadIdx.x;
    const int tx = tid & 15;
    const int ty = tid >> 4;
    const int q0 = blockIdx.x * 64;
    const int h = blockIdx.y;
    const int b = blockIdx.z;

    const size_t head_off = ((size_t)(b * NHEAD + h)) * SEQ * HEAD_DIM;
    const float* __restrict__ Qg = g_Q + head_off;
    const float* __restrict__ Kg = g_K + head_off;
    const float* __restrict__ Vg = g_V + head_off;

    // Load Q tile [64 x 64] into Qs[row*68 + s]
    #pragma unroll
    for (int it = 0; it < 4; it++) {
        int idx = tid + it * 256;        // float4 index, 0..1023
        int row = idx >> 4;
        int sc  = (idx & 15) * 4;
        *(float4*)&Qs[row * AT_STRIDE + sc] =
            *(const float4*)(Qg + (size_t)(q0 + row) * HEAD_DIM + sc);
    }

    float m_[4], l_[4], O[4][4];
    #pragma unroll
    for (int i = 0; i < 4; i++) {
        m_[i] = -INFINITY;
        l_[i] = 0.0f;
        #pragma unroll
        for (int j = 0; j < 4; j++) O[i][j] = 0.0f;
    }

    for (int k0 = 0; k0 < SEQ; k0 += 64) {
        __syncthreads();   // previous iteration done with KPs/Vs
        #pragma unroll
        for (int it = 0; it < 4; it++) {
            int idx = tid + it * 256;
            int row = idx >> 4;
            int sc  = (idx & 15) * 4;
            *(float4*)&KPs[row * AT_STRIDE + sc] =
                *(const float4*)(Kg + (size_t)(k0 + row) * HEAD_DIM + sc);
            *(float4*)&Vs[row * AT_STRIDE + sc] =
                *(const float4*)(Vg + (size_t)(k0 + row) * HEAD_DIM + sc);
        }
        __syncthreads();

        // S = Q . K^T for this thread's 4x4
        float s_[4][4];
        #pragma unroll
        for (int i = 0; i < 4; i++)
            #pragma unroll
            for (int j = 0; j < 4; j++) s_[i][j] = 0.0f;

        #pragma unroll
        for (int s4 = 0; s4 < 16; s4++) {
            float4 q[4], kv[4];
            #pragma unroll
            for (int i = 0; i < 4; i++)
                q[i] = *(const float4*)&Qs[(ty + 16 * i) * AT_STRIDE + s4 * 4];
            #pragma unroll
            for (int j = 0; j < 4; j++)
                kv[j] = *(const float4*)&KPs[(tx + 16 * j) * AT_STRIDE + s4 * 4];
            #pragma unroll
            for (int i = 0; i < 4; i++)
                #pragma unroll
                for (int j = 0; j < 4; j++)
                    s_[i][j] += q[i].x * kv[j].x + q[i].y * kv[j].y
                              + q[i].z * kv[j].z + q[i].w * kv[j].w;
        }
        __syncthreads();   // all threads finished reading KPs as K tile

        // Online softmax update; write P into KPs (aliased)
        #pragma unroll
        for (int i = 0; i < 4; i++) {
            int qr = q0 + ty + 16 * i;
            float x[4];
            float tm = -INFINITY;
            #pragma unroll
            for (int j = 0; j < 4; j++) {
                x[j] = s_[i][j] * 0.125f
                     + mask[(size_t)qr * SEQ + k0 + tx + 16 * j];
                tm = fmaxf(tm, x[j]);
            }
            #pragma unroll
            for (int off = 1; off < 16; off <<= 1)
                tm = fmaxf(tm, __shfl_xor_sync(0xffffffffu, tm, off));
            float mn = fmaxf(m_[i], tm);
            float corr = __expf(m_[i] - mn);
            float rs = 0.0f;
            #pragma unroll
            for (int j = 0; j < 4; j++) {
                x[j] = __expf(x[j] - mn);
                rs += x[j];
            }
            #pragma unroll
            for (int off = 1; off < 16; off <<= 1)
                rs += __shfl_xor_sync(0xffffffffu, rs, off);
            l_[i] = l_[i] * corr + rs;
            m_[i] = mn;
            #pragma unroll
            for (int j = 0; j < 4; j++) {
                O[i][j] *= corr;
                KPs[(ty + 16 * i) * AT_STRIDE + tx + 16 * j] = x[j];
            }
        }
        __syncthreads();   // P tile visible

        // O += P @ V
        #pragma unroll 4
        for (int kk = 0; kk < 64; kk++) {
            float p0 = KPs[(ty +  0) * AT_STRIDE + kk];
            float p1 = KPs[(ty + 16) * AT_STRIDE + kk];
            float p2 = KPs[(ty + 32) * AT_STRIDE + kk];
            float p3 = KPs[(ty + 48) * AT_STRIDE + kk];
            float v0 = Vs[kk * AT_STRIDE + tx +  0];
            float v1 = Vs[kk * AT_STRIDE + tx + 16];
            float v2 = Vs[kk * AT_STRIDE + tx + 32];
            float v3 = Vs[kk * AT_STRIDE + tx + 48];
            O[0][0] += p0 * v0; O[0][1] += p0 * v1; O[0][2] += p0 * v2; O[0][3] += p0 * v3;
            O[1][0] += p1 * v0; O[1][1] += p1 * v1; O[1][2] += p1 * v2; O[1][3] += p1 * v3;
            O[2][0] += p2 * v0; O[2][1] += p2 * v1; O[2][2] += p2 * v2; O[2][3] += p2 * v3;
            O[3][0] += p3 * v0; O[3][1] += p3 * v1; O[3][2] += p3 * v2; O[3][3] += p3 * v3;
        }
    }

    // Write O / l to out [B, L, D]
    #pragma unroll
    for (int i = 0; i < 4; i++) {
        float inv = 1.0f / l_[i];
        int qr = q0 + ty + 16 * i;
        #pragma unroll
        for (int j = 0; j < 4; j++) {
            out[((size_t)b * SEQ + qr) * D_MODEL + h * HEAD_DIM + tx + 16 * j]
                = O[i][j] * inv;
        }
    }
}

// ---------------------------------------------------------------------------
// Launch
// inputs: 0=data 1=temporal 2=mask 3=Wq 4=bq 5=Wk 6=bk 7=Wv 8=bv
// ---------------------------------------------------------------------------
extern "C" void kernel_launch(void* const* d_in, const int* in_sizes, int n_in,
                              void* d_out, int out_size)
{
    const float* data     = (const float*)d_in[0];
    const float* temporal = (const float*)d_in[1];
    const float* mask     = (const float*)d_in[2];
    const float* Wq = (const float*)d_in[3];
    const float* bq = (const float*)d_in[4];
    const float* Wk = (const float*)d_in[5];
    const float* bk = (const float*)d_in[6];
    const float* Wv = (const float*)d_in[7];
    const float* bv = (const float*)d_in[8];
    float* out = (float*)d_out;

    cudaFuncSetAttribute(flash_attn_kernel,
                         cudaFuncAttributeMaxDynamicSharedMemorySize,
                         AT_SMEM_BYTES);

    dim3 g1(M_TOT / 64, D_MODEL / 64, 3);
    qkv_rope_kernel<<<g1, 256>>>(data, temporal, Wq, bq, Wk, bk, Wv, bv);

    dim3 g2(SEQ / 64, NHEAD, BATCH);
    flash_attn_kernel<<<g2, 256, AT_SMEM_BYTES>>>(mask, out);
}

// round 5
// speedup vs baseline: 2.3911x; 2.3911x over previous
#include <cuda_runtime.h>
#include <cuda_bf16.h>
#include <math.h>
#include <stdint.h>

#define D_MODEL 1024
#define NHEAD   16
#define HEAD_DIM 64
#define BATCH   2
#define SEQ     2048
#define M_TOT   (BATCH*SEQ)          // 4096

// bf16 hi/lo scratch
__device__ __nv_bfloat16 g_Qh[BATCH*NHEAD*SEQ*HEAD_DIM];
__device__ __nv_bfloat16 g_Ql[BATCH*NHEAD*SEQ*HEAD_DIM];
__device__ __nv_bfloat16 g_Kh[BATCH*NHEAD*SEQ*HEAD_DIM];
__device__ __nv_bfloat16 g_Kl[BATCH*NHEAD*SEQ*HEAD_DIM];
__device__ __nv_bfloat16 g_Vh[BATCH*NHEAD*SEQ*HEAD_DIM];
__device__ __nv_bfloat16 g_Vl[BATCH*NHEAD*SEQ*HEAD_DIM];
__device__ __nv_bfloat16 g_Dh[M_TOT*D_MODEL];
__device__ __nv_bfloat16 g_Dl[M_TOT*D_MODEL];
__device__ __nv_bfloat16 g_Wh[3*D_MODEL*D_MODEL];
__device__ __nv_bfloat16 g_Wl[3*D_MODEL*D_MODEL];

#define LOG2_10K 13.287712379549449f

// ===========================================================================
// mma.sync / ldmatrix helpers (sm_80+, no arch-'a' gating)
// ===========================================================================
__device__ __forceinline__ uint32_t smem_u32(const void* p) {
    uint32_t a;
    asm("{ .reg .u64 t; cvta.to.shared.u64 t, %1; cvt.u32.u64 %0, t; }"
        : "=r"(a) : "l"(p));
    return a;
}
__device__ __forceinline__ void ldsm_x4(uint32_t* r, uint32_t addr) {
    asm volatile("ldmatrix.sync.aligned.m8n8.x4.shared.b16 {%0,%1,%2,%3}, [%4];"
        : "=r"(r[0]), "=r"(r[1]), "=r"(r[2]), "=r"(r[3]) : "r"(addr));
}
__device__ __forceinline__ void ldsm_x2(uint32_t* r, uint32_t addr) {
    asm volatile("ldmatrix.sync.aligned.m8n8.x2.shared.b16 {%0,%1}, [%2];"
        : "=r"(r[0]), "=r"(r[1]) : "r"(addr));
}
__device__ __forceinline__ void ldsm_x2t(uint32_t* r, uint32_t addr) {
    asm volatile("ldmatrix.sync.aligned.m8n8.x2.trans.shared.b16 {%0,%1}, [%2];"
        : "=r"(r[0]), "=r"(r[1]) : "r"(addr));
}
__device__ __forceinline__ void mma16816(float* c, const uint32_t* a, const uint32_t* b) {
    asm volatile("mma.sync.aligned.m16n8k16.row.col.f32.bf16.bf16.f32 "
        "{%0,%1,%2,%3}, {%4,%5,%6,%7}, {%8,%9}, {%0,%1,%2,%3};"
        : "+f"(c[0]), "+f"(c[1]), "+f"(c[2]), "+f"(c[3])
        : "r"(a[0]), "r"(a[1]), "r"(a[2]), "r"(a[3]), "r"(b[0]), "r"(b[1]));
}

union BF2U { __nv_bfloat162 b2; unsigned u; };

__device__ __forceinline__ unsigned packbf(float x, float y) {
    BF2U u; u.b2 = __floats2bfloat162_rn(x, y); return u.u;
}
__device__ __forceinline__ float2 unpackbf(unsigned v) {
    BF2U u; u.u = v;
    return make_float2(__bfloat162float(u.b2.x), __bfloat162float(u.b2.y));
}

__device__ __forceinline__ void split4(float4 v, uint2& hi, uint2& lo) {
    BF2U h0, h1, l0, l1;
    h0.b2 = __floats2bfloat162_rn(v.x, v.y);
    h1.b2 = __floats2bfloat162_rn(v.z, v.w);
    l0.b2 = __floats2bfloat162_rn(v.x - __bfloat162float(h0.b2.x),
                                  v.y - __bfloat162float(h0.b2.y));
    l1.b2 = __floats2bfloat162_rn(v.z - __bfloat162float(h1.b2.x),
                                  v.w - __bfloat162float(h1.b2.y));
    hi = make_uint2(h0.u, h1.u);
    lo = make_uint2(l0.u, l1.u);
}

// ===========================================================================
// Split kernels
// ===========================================================================
__global__ __launch_bounds__(256) void dsplit_kernel(const float* __restrict__ src) {
    int idx = blockIdx.x * 256 + threadIdx.x;
    float4 v = *(const float4*)(src + (size_t)idx * 4);
    uint2 hi, lo;
    split4(v, hi, lo);
    *(uint2*)(g_Dh + (size_t)idx * 4) = hi;
    *(uint2*)(g_Dl + (size_t)idx * 4) = lo;
}

__global__ __launch_bounds__(256) void wsplit_kernel(const float* __restrict__ W, int mat) {
    __shared__ __nv_bfloat16 th[32][40];
    __shared__ __nv_bfloat16 tl[32][40];
    const int tid = threadIdx.x;
    const int k0 = blockIdx.x * 32;
    const int n0 = blockIdx.y * 32;
    {
        int r = tid >> 3, c4 = (tid & 7) * 4;
        float4 v = *(const float4*)(W + (size_t)(k0 + r) * D_MODEL + n0 + c4);
        uint2 hi, lo;
        split4(v, hi, lo);
        *(uint2*)&th[r][c4] = hi;
        *(uint2*)&tl[r][c4] = lo;
    }
    __syncthreads();
    {
        int r = tid >> 3, c4 = (tid & 7) * 4;
        __nv_bfloat16 hh[4], ll[4];
        #pragma unroll
        for (int j = 0; j < 4; ++j) { hh[j] = th[c4 + j][r]; ll[j] = tl[c4 + j][r]; }
        size_t o = ((size_t)mat << 20) + (size_t)(n0 + r) * D_MODEL + k0 + c4;
        *(uint2*)(g_Wh + o) = *(uint2*)hh;
        *(uint2*)(g_Wl + o) = *(uint2*)ll;
    }
}

// ===========================================================================
// QKV GEMM via bf16 HMMA hi/lo 3-pass. 128x128 tile, BK=32, 8 warps (2x4).
// Epilogue: bias + RoPE, hi/lo split output to [B,H,L,S].
// ===========================================================================
#define ASTR 40

__global__ __launch_bounds__(256, 1) void qkv_mma_kernel(
    const float* __restrict__ temporal,
    const float* __restrict__ bq, const float* __restrict__ bk,
    const float* __restrict__ bv)
{
    __shared__ __nv_bfloat16 sAh[128][ASTR];
    __shared__ __nv_bfloat16 sAl[128][ASTR];
    __shared__ __nv_bfloat16 sBh[128][ASTR];
    __shared__ __nv_bfloat16 sBl[128][ASTR];

    const int mat = blockIdx.z;
    const float* __restrict__ bias = (mat == 0) ? bq : ((mat == 1) ? bk : bv);
    __nv_bfloat16* __restrict__ outH = (mat == 0) ? g_Qh : ((mat == 1) ? g_Kh : g_Vh);
    __nv_bfloat16* __restrict__ outL = (mat == 0) ? g_Ql : ((mat == 1) ? g_Kl : g_Vl);
    const __nv_bfloat16* __restrict__ Wh = g_Wh + ((size_t)mat << 20);
    const __nv_bfloat16* __restrict__ Wl = g_Wl + ((size_t)mat << 20);

    const int tid = threadIdx.x;
    const int lane = tid & 31;
    const int wid = tid >> 5;
    const int wm = wid & 1;
    const int wn = wid >> 1;
    const int m0 = blockIdx.x * 128;
    const int n0 = blockIdx.y * 128;

    const uint32_t baseAh = smem_u32(&sAh[0][0]);
    const uint32_t baseAl = smem_u32(&sAl[0][0]);
    const uint32_t baseBh = smem_u32(&sBh[0][0]);
    const uint32_t baseBl = smem_u32(&sBl[0][0]);

    float acc[4][4][4];
    #pragma unroll
    for (int i = 0; i < 4; ++i)
        #pragma unroll
        for (int j = 0; j < 4; ++j)
            #pragma unroll
            for (int e = 0; e < 4; ++e) acc[i][j][e] = 0.0f;

    const int lrow = tid >> 3;
    const int lc4  = (tid & 7) * 4;

    for (int kk = 0; kk < D_MODEL; kk += 32) {
        #pragma unroll
        for (int it = 0; it < 4; ++it) {
            int row = lrow + it * 32;
            size_t go = (size_t)(m0 + row) * D_MODEL + kk + lc4;
            *(uint2*)&sAh[row][lc4] = *(const uint2*)(g_Dh + go);
            *(uint2*)&sAl[row][lc4] = *(const uint2*)(g_Dl + go);
            size_t wo = (size_t)(n0 + row) * D_MODEL + kk + lc4;
            *(uint2*)&sBh[row][lc4] = *(const uint2*)(Wh + wo);
            *(uint2*)&sBl[row][lc4] = *(const uint2*)(Wl + wo);
        }
        __syncthreads();

        #pragma unroll
        for (int ks = 0; ks < 2; ++ks) {
            const int ko = ks * 16;
            uint32_t Ah[4][4], Al[4][4], Bh[4][2], Bl[4][2];
            const uint32_t aoff = (uint32_t)((wm * 64 + (lane & 15)) * ASTR
                                             + ko + ((lane >> 4) << 3)) * 2;
            #pragma unroll
            for (int ma = 0; ma < 4; ++ma) {
                ldsm_x4(Ah[ma], baseAh + aoff + ma * 16 * ASTR * 2);
                ldsm_x4(Al[ma], baseAl + aoff + ma * 16 * ASTR * 2);
            }
            const uint32_t boff = (uint32_t)((wn * 32 + (lane & 7)) * ASTR
                                             + ko + (((lane >> 3) & 1) << 3)) * 2;
            #pragma unroll
            for (int nb = 0; nb < 4; ++nb) {
                ldsm_x2(Bh[nb], baseBh + boff + nb * 8 * ASTR * 2);
                ldsm_x2(Bl[nb], baseBl + boff + nb * 8 * ASTR * 2);
            }
            #pragma unroll
            for (int ma = 0; ma < 4; ++ma)
                #pragma unroll
                for (int nb = 0; nb < 4; ++nb) {
                    mma16816(acc[ma][nb], Ah[ma], Bh[nb]);
                    mma16816(acc[ma][nb], Al[ma], Bh[nb]);
                    mma16816(acc[ma][nb], Ah[ma], Bl[nb]);
                }
        }
        __syncthreads();
    }

    // Epilogue: bias + RoPE, split to bf16 hi/lo, store [B,H,L,S]
    #pragma unroll
    for (int ma = 0; ma < 4; ++ma) {
        const int r0 = m0 + wm * 64 + ma * 16 + (lane >> 2);
        #pragma unroll
        for (int rg = 0; rg < 2; ++rg) {
            const int r = r0 + rg * 8;
            const int bb = r >> 11;
            const int ll = r & (SEQ - 1);
            float t = 0.0f;
            if (mat < 2) t = temporal[r];
            #pragma unroll
            for (int nb = 0; nb < 4; ++nb) {
                const int n = n0 + wn * 32 + nb * 8 + (lane & 3) * 2;
                const int hh = n >> 6;
                const int s = n & 63;
                float x0 = acc[ma][nb][rg * 2 + 0] + bias[n];
                float x1 = acc[ma][nb][rg * 2 + 1] + bias[n + 1];
                float2 v;
                if (mat < 2) {
                    float f = exp2f(-(float)s * (LOG2_10K / (float)HEAD_DIM));
                    float sn, cs;
                    sincosf(t * f, &sn, &cs);
                    v.x = x0 * cs - x1 * sn;
                    v.y = x1 * cs + x0 * sn;
                } else {
                    v.x = x0; v.y = x1;
                }
                unsigned uh = packbf(v.x, v.y);
                float2 hv = unpackbf(uh);
                unsigned ul = packbf(v.x - hv.x, v.y - hv.y);
                size_t o = (((size_t)(bb * NHEAD + hh)) * SEQ + ll) * HEAD_DIM + s;
                *(unsigned*)(outH + o) = uh;
                *(unsigned*)(outL + o) = ul;
            }
        }
    }
}

// ===========================================================================
// Flash attention via bf16 HMMA hi/lo. Q block 128, K/V tiles 128.
// 8 warps, each owns m16 x n128 strip -> warp-local softmax.
// ===========================================================================
#define FSTR 72
#define T_BYTES (128 * FSTR * 2)
#define O_QH 0
#define O_QL (1 * T_BYTES)
#define O_KH (2 * T_BYTES)
#define O_KL (3 * T_BYTES)
#define O_VH (4 * T_BYTES)
#define O_VL (5 * T_BYTES)
#define AT_SMEM (6 * T_BYTES)

__global__ __launch_bounds__(256, 1) void attn_mma_kernel(
    const float* __restrict__ mask, float* __restrict__ out)
{
    extern __shared__ char smc[];
    const uint32_t base = smem_u32(smc);

    const int tid = threadIdx.x;
    const int lane = tid & 31;
    const int wid = tid >> 5;
    const int q0 = blockIdx.x * 128;
    const int hh = blockIdx.y;
    const int bb = blockIdx.z;

    const size_t hb = ((size_t)(bb * NHEAD + hh)) * SEQ * HEAD_DIM;

    // Load Q tile (hi/lo)
    {
        #pragma unroll
        for (int it = 0; it < 4; ++it) {
            int idx = tid + it * 256;
            int row = idx >> 3;
            int c8  = (idx & 7) * 8;
            size_t g = hb + (size_t)(q0 + row) * HEAD_DIM + c8;
            *(uint4*)(smc + O_QH + (row * FSTR + c8) * 2) = *(const uint4*)(g_Qh + g);
            *(uint4*)(smc + O_QL + (row * FSTR + c8) * 2) = *(const uint4*)(g_Ql + g);
        }
    }

    float O[8][4];
    #pragma unroll
    for (int i = 0; i < 8; ++i)
        #pragma unroll
        for (int e = 0; e < 4; ++e) O[i][e] = 0.0f;
    float mrow[2] = {-INFINITY, -INFINITY};
    float lrow[2] = {0.0f, 0.0f};

    const int r0 = lane >> 2;                 // 0..7
    const int qr0 = q0 + wid * 16 + r0;       // rg0 global row; rg1 = +8
    const int cq = (lane & 3) * 2;            // col pair base within n8

    for (int k0 = 0; k0 < SEQ; k0 += 128) {
        __syncthreads();
        #pragma unroll
        for (int it = 0; it < 4; ++it) {
            int idx = tid + it * 256;
            int row = idx >> 3;
            int c8  = (idx & 7) * 8;
            size_t g = hb + (size_t)(k0 + row) * HEAD_DIM + c8;
            int so = (row * FSTR + c8) * 2;
            *(uint4*)(smc + O_KH + so) = *(const uint4*)(g_Kh + g);
            *(uint4*)(smc + O_KL + so) = *(const uint4*)(g_Kl + g);
            *(uint4*)(smc + O_VH + so) = *(const uint4*)(g_Vh + g);
            *(uint4*)(smc + O_VL + so) = *(const uint4*)(g_Vl + g);
        }
        __syncthreads();

        // --- S = Q.K^T (3-pass), warp strip m16 x n128 ---
        float acc[16][4];
        #pragma unroll
        for (int i = 0; i < 16; ++i)
            #pragma unroll
            for (int e = 0; e < 4; ++e) acc[i][e] = 0.0f;

        #pragma unroll
        for (int ks = 0; ks < 4; ++ks) {
            uint32_t Ah[4], Al[4];
            const uint32_t aoff = (uint32_t)((wid * 16 + (lane & 15)) * FSTR
                                             + ks * 16 + ((lane >> 4) << 3)) * 2;
            ldsm_x4(Ah, base + O_QH + aoff);
            ldsm_x4(Al, base + O_QL + aoff);
            #pragma unroll
            for (int nb = 0; nb < 16; ++nb) {
                uint32_t Bh[2], Bl[2];
                const uint32_t boff = (uint32_t)((nb * 8 + (lane & 7)) * FSTR
                                                 + ks * 16 + (((lane >> 3) & 1) << 3)) * 2;
                ldsm_x2(Bh, base + O_KH + boff);
                ldsm_x2(Bl, base + O_KL + boff);
                mma16816(acc[nb], Ah, Bh);
                mma16816(acc[nb], Al, Bh);
                mma16816(acc[nb], Ah, Bl);
            }
        }

        // --- online softmax (warp-local, quad shuffles) ---
        #pragma unroll
        for (int rg = 0; rg < 2; ++rg) {
            const float* mp = mask + (size_t)(qr0 + rg * 8) * SEQ + k0;
            float tm = -INFINITY;
            #pragma unroll
            for (int nb = 0; nb < 16; ++nb) {
                float2 mv = *(const float2*)(mp + nb * 8 + cq);
                float x0 = acc[nb][rg * 2 + 0] * 0.125f + mv.x;
                float x1 = acc[nb][rg * 2 + 1] * 0.125f + mv.y;
                acc[nb][rg * 2 + 0] = x0;
                acc[nb][rg * 2 + 1] = x1;
                tm = fmaxf(tm, fmaxf(x0, x1));
            }
            tm = fmaxf(tm, __shfl_xor_sync(0xffffffffu, tm, 1));
            tm = fmaxf(tm, __shfl_xor_sync(0xffffffffu, tm, 2));
            float mn = fmaxf(mrow[rg], tm);
            float corr = __expf(mrow[rg] - mn);
            float rs = 0.0f;
            #pragma unroll
            for (int nb = 0; nb < 16; ++nb) {
                float p0 = __expf(acc[nb][rg * 2 + 0] - mn);
                float p1 = __expf(acc[nb][rg * 2 + 1] - mn);
                acc[nb][rg * 2 + 0] = p0;
                acc[nb][rg * 2 + 1] = p1;
                rs += p0 + p1;
            }
            rs += __shfl_xor_sync(0xffffffffu, rs, 1);
            rs += __shfl_xor_sync(0xffffffffu, rs, 2);
            lrow[rg] = lrow[rg] * corr + rs;
            mrow[rg] = mn;
            #pragma unroll
            for (int nb = 0; nb < 8; ++nb) {
                O[nb][rg * 2 + 0] *= corr;
                O[nb][rg * 2 + 1] *= corr;
            }
        }

        // --- O += P.V (3-pass), P re-packed from acc registers ---
        #pragma unroll
        for (int ks = 0; ks < 8; ++ks) {
            uint32_t ph[4], pl[4];
            #pragma unroll
            for (int half = 0; half < 2; ++half) {      // half=0: rows rg grouping by frag
                const float* a0 = acc[2 * ks + half];
                // frag index: half -> a[half? 2:0] pattern
                // a0regs: vals 0,1 = row r0; 2,3 = row r0+8
                unsigned h01 = packbf(a0[0], a0[1]);
                unsigned h23 = packbf(a0[2], a0[3]);
                float2 f01 = unpackbf(h01);
                float2 f23 = unpackbf(h23);
                unsigned l01 = packbf(a0[0] - f01.x, a0[1] - f01.y);
                unsigned l23 = packbf(a0[2] - f23.x, a0[3] - f23.y);
                ph[half * 2 + 0] = h01; ph[half * 2 + 1] = h23;
                pl[half * 2 + 0] = l01; pl[half * 2 + 1] = l23;
            }
            #pragma unroll
            for (int nb = 0; nb < 8; ++nb) {
                uint32_t Bh[2], Bl[2];
                const uint32_t voff = (uint32_t)((ks * 16 + (((lane >> 3) & 1) << 3)
                                                  + (lane & 7)) * FSTR + nb * 8) * 2;
                ldsm_x2t(Bh, base + O_VH + voff);
                ldsm_x2t(Bl, base + O_VL + voff);
                mma16816(O[nb], ph, Bh);
                mma16816(O[nb], pl, Bh);
                mma16816(O[nb], ph, Bl);
            }
        }
    }

    // Epilogue: normalize, write out [B, L, D]
    float inv0 = 1.0f / lrow[0];
    float inv1 = 1.0f / lrow[1];
    #pragma unroll
    for (int rg = 0; rg < 2; ++rg) {
        float inv = rg ? inv1 : inv0;
        size_t ob = (size_t)(bb * SEQ + qr0 + rg * 8) * D_MODEL + hh * HEAD_DIM;
        #pragma unroll
        for (int nb = 0; nb < 8; ++nb) {
            float2 v = make_float2(O[nb][rg * 2 + 0] * inv, O[nb][rg * 2 + 1] * inv);
            *(float2*)(out + ob + nb * 8 + cq) = v;
        }
    }
}

// ---------------------------------------------------------------------------
// Launch. inputs: 0=data 1=temporal 2=mask 3=Wq 4=bq 5=Wk 6=bk 7=Wv 8=bv
// ---------------------------------------------------------------------------
extern "C" void kernel_launch(void* const* d_in, const int* in_sizes, int n_in,
                              void* d_out, int out_size)
{
    const float* data     = (const float*)d_in[0];
    const float* temporal = (const float*)d_in[1];
    const float* mask     = (const float*)d_in[2];
    const float* Wq = (const float*)d_in[3];
    const float* bq = (const float*)d_in[4];
    const float* Wk = (const float*)d_in[5];
    const float* bk = (const float*)d_in[6];
    const float* Wv = (const float*)d_in[7];
    const float* bv = (const float*)d_in[8];
    float* out = (float*)d_out;

    cudaFuncSetAttribute(attn_mma_kernel,
                         cudaFuncAttributeMaxDynamicSharedMemorySize, AT_SMEM);

    dsplit_kernel<<<(M_TOT * D_MODEL / 4) / 256, 256>>>(data);
    dim3 gw(D_MODEL / 32, D_MODEL / 32);
    wsplit_kernel<<<gw, 256>>>(Wq, 0);
    wsplit_kernel<<<gw, 256>>>(Wk, 1);
    wsplit_kernel<<<gw, 256>>>(Wv, 2);

    dim3 g1(M_TOT / 128, D_MODEL / 128, 3);
    qkv_mma_kernel<<<g1, 256>>>(temporal, bq, bk, bv);

    dim3 g2(SEQ / 128, NHEAD, BATCH);
    attn_mma_kernel<<<g2, 256, AT_SMEM>>>(mask, out);
}

// round 6
// speedup vs baseline: 2.6624x; 1.1135x over previous
#include <cuda_runtime.h>
#include <cuda_bf16.h>
#include <math.h>
#include <stdint.h>

#define D_MODEL 1024
#define NHEAD   16
#define HEAD_DIM 64
#define BATCH   2
#define SEQ     2048
#define M_TOT   (BATCH*SEQ)          // 4096

// bf16 hi/lo scratch
__device__ __nv_bfloat16 g_Qh[BATCH*NHEAD*SEQ*HEAD_DIM];
__device__ __nv_bfloat16 g_Ql[BATCH*NHEAD*SEQ*HEAD_DIM];
__device__ __nv_bfloat16 g_Kh[BATCH*NHEAD*SEQ*HEAD_DIM];
__device__ __nv_bfloat16 g_Kl[BATCH*NHEAD*SEQ*HEAD_DIM];
__device__ __nv_bfloat16 g_Vh[BATCH*NHEAD*SEQ*HEAD_DIM];
__device__ __nv_bfloat16 g_Vl[BATCH*NHEAD*SEQ*HEAD_DIM];
__device__ __nv_bfloat16 g_Dh[M_TOT*D_MODEL];
__device__ __nv_bfloat16 g_Dl[M_TOT*D_MODEL];
__device__ __nv_bfloat16 g_Wh[3*D_MODEL*D_MODEL];
__device__ __nv_bfloat16 g_Wl[3*D_MODEL*D_MODEL];

#define LOG2_10K 13.287712379549449f

// ===========================================================================
// helpers
// ===========================================================================
__device__ __forceinline__ uint32_t smem_u32(const void* p) {
    uint32_t a;
    asm("{ .reg .u64 t; cvta.to.shared.u64 t, %1; cvt.u32.u64 %0, t; }"
        : "=r"(a) : "l"(p));
    return a;
}
__device__ __forceinline__ void ldsm_x4(uint32_t* r, uint32_t addr) {
    asm volatile("ldmatrix.sync.aligned.m8n8.x4.shared.b16 {%0,%1,%2,%3}, [%4];"
        : "=r"(r[0]), "=r"(r[1]), "=r"(r[2]), "=r"(r[3]) : "r"(addr));
}
__device__ __forceinline__ void ldsm_x4t(uint32_t* r, uint32_t addr) {
    asm volatile("ldmatrix.sync.aligned.m8n8.x4.trans.shared.b16 {%0,%1,%2,%3}, [%4];"
        : "=r"(r[0]), "=r"(r[1]), "=r"(r[2]), "=r"(r[3]) : "r"(addr));
}
__device__ __forceinline__ void mma16816(float* c, const uint32_t* a, const uint32_t* b) {
    asm volatile("mma.sync.aligned.m16n8k16.row.col.f32.bf16.bf16.f32 "
        "{%0,%1,%2,%3}, {%4,%5,%6,%7}, {%8,%9}, {%0,%1,%2,%3};"
        : "+f"(c[0]), "+f"(c[1]), "+f"(c[2]), "+f"(c[3])
        : "r"(a[0]), "r"(a[1]), "r"(a[2]), "r"(a[3]), "r"(b[0]), "r"(b[1]));
}
__device__ __forceinline__ void cp16(uint32_t saddr, const void* g) {
    asm volatile("cp.async.cg.shared.global [%0], [%1], 16;" :: "r"(saddr), "l"(g));
}
#define CP_COMMIT() asm volatile("cp.async.commit_group;" ::: "memory")
#define CP_WAIT0()  asm volatile("cp.async.wait_group 0;" ::: "memory")
#define CP_WAIT1()  asm volatile("cp.async.wait_group 1;" ::: "memory")

union BF2U { __nv_bfloat162 b2; unsigned u; };
__device__ __forceinline__ unsigned packbf(float x, float y) {
    BF2U u; u.b2 = __floats2bfloat162_rn(x, y); return u.u;
}
__device__ __forceinline__ float2 unpackbf(unsigned v) {
    BF2U u; u.u = v;
    return make_float2(__bfloat162float(u.b2.x), __bfloat162float(u.b2.y));
}
__device__ __forceinline__ void split4(float4 v, uint2& hi, uint2& lo) {
    BF2U h0, h1, l0, l1;
    h0.b2 = __floats2bfloat162_rn(v.x, v.y);
    h1.b2 = __floats2bfloat162_rn(v.z, v.w);
    l0.b2 = __floats2bfloat162_rn(v.x - __bfloat162float(h0.b2.x),
                                  v.y - __bfloat162float(h0.b2.y));
    l1.b2 = __floats2bfloat162_rn(v.z - __bfloat162float(h1.b2.x),
                                  v.w - __bfloat162float(h1.b2.y));
    hi = make_uint2(h0.u, h1.u);
    lo = make_uint2(l0.u, l1.u);
}

// ===========================================================================
// Split kernels
// ===========================================================================
__global__ __launch_bounds__(256) void dsplit_kernel(const float* __restrict__ src) {
    int idx = blockIdx.x * 256 + threadIdx.x;
    float4 v = *(const float4*)(src + (size_t)idx * 4);
    uint2 hi, lo;
    split4(v, hi, lo);
    *(uint2*)(g_Dh + (size_t)idx * 4) = hi;
    *(uint2*)(g_Dl + (size_t)idx * 4) = lo;
}

__global__ __launch_bounds__(256) void wsplit_kernel(const float* __restrict__ W, int mat) {
    __shared__ __nv_bfloat16 th[32][40];
    __shared__ __nv_bfloat16 tl[32][40];
    const int tid = threadIdx.x;
    const int k0 = blockIdx.x * 32;
    const int n0 = blockIdx.y * 32;
    {
        int r = tid >> 3, c4 = (tid & 7) * 4;
        float4 v = *(const float4*)(W + (size_t)(k0 + r) * D_MODEL + n0 + c4);
        uint2 hi, lo;
        split4(v, hi, lo);
        *(uint2*)&th[r][c4] = hi;
        *(uint2*)&tl[r][c4] = lo;
    }
    __syncthreads();
    {
        int r = tid >> 3, c4 = (tid & 7) * 4;
        __nv_bfloat16 hh[4], ll[4];
        #pragma unroll
        for (int j = 0; j < 4; ++j) { hh[j] = th[c4 + j][r]; ll[j] = tl[c4 + j][r]; }
        size_t o = ((size_t)mat << 20) + (size_t)(n0 + r) * D_MODEL + k0 + c4;
        *(uint2*)(g_Wh + o) = *(uint2*)hh;
        *(uint2*)(g_Wl + o) = *(uint2*)ll;
    }
}

// ===========================================================================
// QKV GEMM: bf16 HMMA hi/lo 3-pass, 128x128 tile, BK=32, cp.async dbl-buffer.
// ===========================================================================
#define ASTR 40
#define QT_BYTES (128 * ASTR * 2)      // 10240 per tile
#define QBUF_BYTES (4 * QT_BYTES)      // AH, AL, BH, BL
#define QKV_SMEM (2 * QBUF_BYTES)      // 81920

__global__ __launch_bounds__(256) void qkv_mma_kernel(
    const float* __restrict__ temporal,
    const float* __restrict__ bq, const float* __restrict__ bk,
    const float* __restrict__ bv)
{
    extern __shared__ char qsm[];
    const uint32_t base = smem_u32(qsm);

    const int mat = blockIdx.z;
    const float* __restrict__ bias = (mat == 0) ? bq : ((mat == 1) ? bk : bv);
    __nv_bfloat16* __restrict__ outH = (mat == 0) ? g_Qh : ((mat == 1) ? g_Kh : g_Vh);
    __nv_bfloat16* __restrict__ outL = (mat == 0) ? g_Ql : ((mat == 1) ? g_Kl : g_Vl);
    const __nv_bfloat16* __restrict__ Wh = g_Wh + ((size_t)mat << 20);
    const __nv_bfloat16* __restrict__ Wl = g_Wl + ((size_t)mat << 20);

    const int tid = threadIdx.x;
    const int lane = tid & 31;
    const int wid = tid >> 5;
    const int wm = wid & 1;
    const int wn = wid >> 1;
    const int m0 = blockIdx.x * 128;
    const int n0 = blockIdx.y * 128;

    // loader: 512 16B-chunks per tile -> 2 per thread per tile
    const int lrow = tid >> 2;                 // covers 64 rows per 256 threads
    const int lc8  = (tid & 3) * 8;

    auto prefetch = [&](int kk, int buf) {
        uint32_t bb = base + buf * QBUF_BYTES;
        #pragma unroll
        for (int it = 0; it < 2; ++it) {
            int row = lrow + it * 64;
            uint32_t so = (uint32_t)(row * ASTR + lc8) * 2;
            size_t ga = (size_t)(m0 + row) * D_MODEL + kk + lc8;
            size_t gb = (size_t)(n0 + row) * D_MODEL + kk + lc8;
            cp16(bb + so,                 g_Dh + ga);
            cp16(bb + QT_BYTES + so,      g_Dl + ga);
            cp16(bb + 2 * QT_BYTES + so,  Wh + gb);
            cp16(bb + 3 * QT_BYTES + so,  Wl + gb);
        }
    };

    float acc[4][4][4];
    #pragma unroll
    for (int i = 0; i < 4; ++i)
        #pragma unroll
        for (int j = 0; j < 4; ++j)
            #pragma unroll
            for (int e = 0; e < 4; ++e) acc[i][j][e] = 0.0f;

    prefetch(0, 0);
    CP_COMMIT();

    for (int c = 0; c < 32; ++c) {
        __syncthreads();            // all warps done with the buffer being refilled
        if (c + 1 < 32) {
            prefetch((c + 1) * 32, (c + 1) & 1);
            CP_COMMIT();
            CP_WAIT1();
        } else {
            CP_WAIT0();
        }
        __syncthreads();

        const uint32_t bb = base + (c & 1) * QBUF_BYTES;
        const uint32_t bAh = bb;
        const uint32_t bAl = bb + QT_BYTES;
        const uint32_t bBh = bb + 2 * QT_BYTES;
        const uint32_t bBl = bb + 3 * QT_BYTES;

        #pragma unroll
        for (int ks = 0; ks < 2; ++ks) {
            const int ko = ks * 16;
            uint32_t Ah[4][4], Al[4][4], Bh[2][4], Bl[2][4];
            const uint32_t aoff = (uint32_t)((wm * 64 + (lane & 15)) * ASTR
                                             + ko + ((lane >> 4) << 3)) * 2;
            #pragma unroll
            for (int ma = 0; ma < 4; ++ma) {
                ldsm_x4(Ah[ma], bAh + aoff + ma * 16 * ASTR * 2);
                ldsm_x4(Al[ma], bAl + aoff + ma * 16 * ASTR * 2);
            }
            {
                const int m = lane >> 3;
                #pragma unroll
                for (int nbp = 0; nbp < 2; ++nbp) {
                    int rr = wn * 32 + nbp * 16 + ((m >> 1) << 3) + (lane & 7);
                    int cc = ko + ((m & 1) << 3);
                    uint32_t off = (uint32_t)(rr * ASTR + cc) * 2;
                    ldsm_x4(Bh[nbp], bBh + off);
                    ldsm_x4(Bl[nbp], bBl + off);
                }
            }
            #pragma unroll
            for (int ma = 0; ma < 4; ++ma)
                #pragma unroll
                for (int nbp = 0; nbp < 2; ++nbp) {
                    mma16816(acc[ma][2*nbp+0], Ah[ma], Bh[nbp] + 0);
                    mma16816(acc[ma][2*nbp+0], Al[ma], Bh[nbp] + 0);
                    mma16816(acc[ma][2*nbp+0], Ah[ma], Bl[nbp] + 0);
                    mma16816(acc[ma][2*nbp+1], Ah[ma], Bh[nbp] + 2);
                    mma16816(acc[ma][2*nbp+1], Al[ma], Bh[nbp] + 2);
                    mma16816(acc[ma][2*nbp+1], Ah[ma], Bl[nbp] + 2);
                }
        }
    }

    // Epilogue: bias + RoPE, split to bf16 hi/lo, store [B,H,L,S]
    #pragma unroll
    for (int ma = 0; ma < 4; ++ma) {
        const int r0 = m0 + wm * 64 + ma * 16 + (lane >> 2);
        #pragma unroll
        for (int rg = 0; rg < 2; ++rg) {
            const int r = r0 + rg * 8;
            const int bb = r >> 11;
            const int ll = r & (SEQ - 1);
            float t = 0.0f;
            if (mat < 2) t = temporal[r];
            #pragma unroll
            for (int nb = 0; nb < 4; ++nb) {
                const int n = n0 + wn * 32 + nb * 8 + (lane & 3) * 2;
                const int hh = n >> 6;
                const int s = n & 63;
                float x0 = acc[ma][nb][rg * 2 + 0] + bias[n];
                float x1 = acc[ma][nb][rg * 2 + 1] + bias[n + 1];
                float2 v;
                if (mat < 2) {
                    float f = exp2f(-(float)s * (LOG2_10K / (float)HEAD_DIM));
                    float sn, cs;
                    sincosf(t * f, &sn, &cs);
                    v.x = x0 * cs - x1 * sn;
                    v.y = x1 * cs + x0 * sn;
                } else {
                    v.x = x0; v.y = x1;
                }
                unsigned uh = packbf(v.x, v.y);
                float2 hv = unpackbf(uh);
                unsigned ul = packbf(v.x - hv.x, v.y - hv.y);
                size_t o = (((size_t)(bb * NHEAD + hh)) * SEQ + ll) * HEAD_DIM + s;
                *(unsigned*)(outH + o) = uh;
                *(unsigned*)(outL + o) = ul;
            }
        }
    }
}

// ===========================================================================
// Flash attention: bf16 HMMA hi/lo, Q block 128, K/V tiles 128,
// cp.async double-buffered K/V, merged x4 B-frag loads.
// ===========================================================================
#define FSTR 72
#define T_BYTES (128 * FSTR * 2)       // 18432
#define O_QH 0
#define O_QL T_BYTES
#define KVBUF_BYTES (4 * T_BYTES)      // KH, KL, VH, VL
#define AT_SMEM (2 * T_BYTES + 2 * KVBUF_BYTES)   // 184320

__global__ __launch_bounds__(256, 1) void attn_mma_kernel(
    const float* __restrict__ mask, float* __restrict__ out)
{
    extern __shared__ char smc[];
    const uint32_t base = smem_u32(smc);

    const int tid = threadIdx.x;
    const int lane = tid & 31;
    const int wid = tid >> 5;
    const int q0 = blockIdx.x * 128;
    const int hh = blockIdx.y;
    const int bb = blockIdx.z;

    const size_t hb = ((size_t)(bb * NHEAD + hh)) * SEQ * HEAD_DIM;

    const int lrow = tid >> 1;            // 1024 chunks: 128 rows x 8; 4 per thread
    const int lc8  = (tid & 1) * 8;       // used with it-stride below

    // Q prefetch (group together with first K/V buffer)
    {
        #pragma unroll
        for (int it = 0; it < 4; ++it) {
            int idx = tid + it * 256;
            int row = idx >> 3;
            int c8  = (idx & 7) * 8;
            uint32_t so = (uint32_t)(row * FSTR + c8) * 2;
            size_t g = hb + (size_t)(q0 + row) * HEAD_DIM + c8;
            cp16(base + O_QH + so, g_Qh + g);
            cp16(base + O_QL + so, g_Ql + g);
        }
    }
    auto prefetch_kv = [&](int k0, int buf) {
        uint32_t bbse = base + 2 * T_BYTES + buf * KVBUF_BYTES;
        #pragma unroll
        for (int it = 0; it < 4; ++it) {
            int idx = tid + it * 256;
            int row = idx >> 3;
            int c8  = (idx & 7) * 8;
            uint32_t so = (uint32_t)(row * FSTR + c8) * 2;
            size_t g = hb + (size_t)(k0 + row) * HEAD_DIM + c8;
            cp16(bbse + so,               g_Kh + g);
            cp16(bbse + T_BYTES + so,     g_Kl + g);
            cp16(bbse + 2 * T_BYTES + so, g_Vh + g);
            cp16(bbse + 3 * T_BYTES + so, g_Vl + g);
        }
    };
    prefetch_kv(0, 0);
    CP_COMMIT();

    float O[8][4];
    #pragma unroll
    for (int i = 0; i < 8; ++i)
        #pragma unroll
        for (int e = 0; e < 4; ++e) O[i][e] = 0.0f;
    float mrow[2] = {-INFINITY, -INFINITY};
    float lrow_[2] = {0.0f, 0.0f};

    const int r0 = lane >> 2;
    const int qr0 = q0 + wid * 16 + r0;
    const int cq = (lane & 3) * 2;

    const int NIT = SEQ / 128;
    for (int c = 0; c < NIT; ++c) {
        __syncthreads();
        if (c + 1 < NIT) {
            prefetch_kv((c + 1) * 128, (c + 1) & 1);
            CP_COMMIT();
            CP_WAIT1();
        } else {
            CP_WAIT0();
        }
        __syncthreads();

        const uint32_t bufb = base + 2 * T_BYTES + (c & 1) * KVBUF_BYTES;
        const uint32_t bKH = bufb;
        const uint32_t bKL = bufb + T_BYTES;
        const uint32_t bVH = bufb + 2 * T_BYTES;
        const uint32_t bVL = bufb + 3 * T_BYTES;
        const int k0 = c * 128;

        // --- S = Q.K^T (3-pass), warp strip m16 x n128 ---
        float acc[16][4];
        #pragma unroll
        for (int i = 0; i < 16; ++i)
            #pragma unroll
            for (int e = 0; e < 4; ++e) acc[i][e] = 0.0f;

        const int m = lane >> 3;
        #pragma unroll
        for (int ks = 0; ks < 4; ++ks) {
            uint32_t Ah[4], Al[4];
            const uint32_t aoff = (uint32_t)((wid * 16 + (lane & 15)) * FSTR
                                             + ks * 16 + ((lane >> 4) << 3)) * 2;
            ldsm_x4(Ah, base + O_QH + aoff);
            ldsm_x4(Al, base + O_QL + aoff);
            #pragma unroll
            for (int nbp = 0; nbp < 8; ++nbp) {
                uint32_t Bh[4], Bl[4];
                int rr = nbp * 16 + ((m >> 1) << 3) + (lane & 7);
                int cc = ks * 16 + ((m & 1) << 3);
                uint32_t off = (uint32_t)(rr * FSTR + cc) * 2;
                ldsm_x4(Bh, bKH + off);
                ldsm_x4(Bl, bKL + off);
                mma16816(acc[2*nbp+0], Ah, Bh + 0);
                mma16816(acc[2*nbp+0], Al, Bh + 0);
                mma16816(acc[2*nbp+0], Ah, Bl + 0);
                mma16816(acc[2*nbp+1], Ah, Bh + 2);
                mma16816(acc[2*nbp+1], Al, Bh + 2);
                mma16816(acc[2*nbp+1], Ah, Bl + 2);
            }
        }

        // --- online softmax (warp-local, quad shuffles) ---
        #pragma unroll
        for (int rg = 0; rg < 2; ++rg) {
            const float* mp = mask + (size_t)(qr0 + rg * 8) * SEQ + k0;
            float tm = -INFINITY;
            #pragma unroll
            for (int nb = 0; nb < 16; ++nb) {
                float2 mv = *(const float2*)(mp + nb * 8 + cq);
                float x0 = acc[nb][rg * 2 + 0] * 0.125f + mv.x;
                float x1 = acc[nb][rg * 2 + 1] * 0.125f + mv.y;
                acc[nb][rg * 2 + 0] = x0;
                acc[nb][rg * 2 + 1] = x1;
                tm = fmaxf(tm, fmaxf(x0, x1));
            }
            tm = fmaxf(tm, __shfl_xor_sync(0xffffffffu, tm, 1));
            tm = fmaxf(tm, __shfl_xor_sync(0xffffffffu, tm, 2));
            float mn = fmaxf(mrow[rg], tm);
            float corr = __expf(mrow[rg] - mn);
            float rs = 0.0f;
            #pragma unroll
            for (int nb = 0; nb < 16; ++nb) {
                float p0 = __expf(acc[nb][rg * 2 + 0] - mn);
                float p1 = __expf(acc[nb][rg * 2 + 1] - mn);
                acc[nb][rg * 2 + 0] = p0;
                acc[nb][rg * 2 + 1] = p1;
                rs += p0 + p1;
            }
            rs += __shfl_xor_sync(0xffffffffu, rs, 1);
            rs += __shfl_xor_sync(0xffffffffu, rs, 2);
            lrow_[rg] = lrow_[rg] * corr + rs;
            mrow[rg] = mn;
            #pragma unroll
            for (int nb = 0; nb < 8; ++nb) {
                O[nb][rg * 2 + 0] *= corr;
                O[nb][rg * 2 + 1] *= corr;
            }
        }

        // --- O += P.V (3-pass), P re-packed from registers ---
        #pragma unroll
        for (int ks = 0; ks < 8; ++ks) {
            uint32_t ph[4], pl[4];
            #pragma unroll
            for (int half = 0; half < 2; ++half) {
                const float* a0 = acc[2 * ks + half];
                unsigned h01 = packbf(a0[0], a0[1]);
                unsigned h23 = packbf(a0[2], a0[3]);
                float2 f01 = unpackbf(h01);
                float2 f23 = unpackbf(h23);
                unsigned l01 = packbf(a0[0] - f01.x, a0[1] - f01.y);
                unsigned l23 = packbf(a0[2] - f23.x, a0[3] - f23.y);
                ph[half * 2 + 0] = h01; ph[half * 2 + 1] = h23;
                pl[half * 2 + 0] = l01; pl[half * 2 + 1] = l23;
            }
            #pragma unroll
            for (int nbp = 0; nbp < 4; ++nbp) {
                uint32_t Vh[4], Vl[4];
                int rr = ks * 16 + ((m & 1) << 3) + (lane & 7);
                int cc = nbp * 16 + ((m >> 1) << 3);
                uint32_t off = (uint32_t)(rr * FSTR + cc) * 2;
                ldsm_x4t(Vh, bVH + off);
                ldsm_x4t(Vl, bVL + off);
                mma16816(O[2*nbp+0], ph, Vh + 0);
                mma16816(O[2*nbp+0], pl, Vh + 0);
                mma16816(O[2*nbp+0], ph, Vl + 0);
                mma16816(O[2*nbp+1], ph, Vh + 2);
                mma16816(O[2*nbp+1], pl, Vh + 2);
                mma16816(O[2*nbp+1], ph, Vl + 2);
            }
        }
    }

    // Epilogue
    float inv0 = 1.0f / lrow_[0];
    float inv1 = 1.0f / lrow_[1];
    #pragma unroll
    for (int rg = 0; rg < 2; ++rg) {
        float inv = rg ? inv1 : inv0;
        size_t ob = (size_t)(bb * SEQ + qr0 + rg * 8) * D_MODEL + hh * HEAD_DIM;
        #pragma unroll
        for (int nb = 0; nb < 8; ++nb) {
            float2 v = make_float2(O[nb][rg * 2 + 0] * inv, O[nb][rg * 2 + 1] * inv);
            *(float2*)(out + ob + nb * 8 + cq) = v;
        }
    }
    (void)lrow; (void)lc8;
}

// ---------------------------------------------------------------------------
// Launch. inputs: 0=data 1=temporal 2=mask 3=Wq 4=bq 5=Wk 6=bk 7=Wv 8=bv
// ---------------------------------------------------------------------------
extern "C" void kernel_launch(void* const* d_in, const int* in_sizes, int n_in,
                              void* d_out, int out_size)
{
    const float* data     = (const float*)d_in[0];
    const float* temporal = (const float*)d_in[1];
    const float* mask     = (const float*)d_in[2];
    const float* Wq = (const float*)d_in[3];
    const float* bq = (const float*)d_in[4];
    const float* Wk = (const float*)d_in[5];
    const float* bk = (const float*)d_in[6];
    const float* Wv = (const float*)d_in[7];
    const float* bv = (const float*)d_in[8];
    float* out = (float*)d_out;

    cudaFuncSetAttribute(qkv_mma_kernel,
                         cudaFuncAttributeMaxDynamicSharedMemorySize, QKV_SMEM);
    cudaFuncSetAttribute(attn_mma_kernel,
                         cudaFuncAttributeMaxDynamicSharedMemorySize, AT_SMEM);

    dsplit_kernel<<<(M_TOT * D_MODEL / 4) / 256, 256>>>(data);
    dim3 gw(D_MODEL / 32, D_MODEL / 32);
    wsplit_kernel<<<gw, 256>>>(Wq, 0);
    wsplit_kernel<<<gw, 256>>>(Wk, 1);
    wsplit_kernel<<<gw, 256>>>(Wv, 2);

    dim3 g1(M_TOT / 128, D_MODEL / 128, 3);
    qkv_mma_kernel<<<g1, 256, QKV_SMEM>>>(temporal, bq, bk, bv);

    dim3 g2(SEQ / 128, NHEAD, BATCH);
    attn_mma_kernel<<<g2, 256, AT_SMEM>>>(mask, out);
}

// round 8
// speedup vs baseline: 2.8170x; 1.0581x over previous
#include <cuda_runtime.h>
#include <cuda_bf16.h>
#include <math.h>
#include <stdint.h>

#define D_MODEL 1024
#define NHEAD   16
#define HEAD_DIM 64
#define BATCH   2
#define SEQ     2048
#define M_TOT   (BATCH*SEQ)          // 4096

// bf16 hi/lo scratch
__device__ __nv_bfloat16 g_Qh[BATCH*NHEAD*SEQ*HEAD_DIM];
__device__ __nv_bfloat16 g_Ql[BATCH*NHEAD*SEQ*HEAD_DIM];
__device__ __nv_bfloat16 g_Kh[BATCH*NHEAD*SEQ*HEAD_DIM];
__device__ __nv_bfloat16 g_Kl[BATCH*NHEAD*SEQ*HEAD_DIM];
__device__ __nv_bfloat16 g_Vh[BATCH*NHEAD*SEQ*HEAD_DIM];
__device__ __nv_bfloat16 g_Vl[BATCH*NHEAD*SEQ*HEAD_DIM];
__device__ __nv_bfloat16 g_Dh[M_TOT*D_MODEL];
__device__ __nv_bfloat16 g_Dl[M_TOT*D_MODEL];
__device__ __nv_bfloat16 g_Wh[3*D_MODEL*D_MODEL];
__device__ __nv_bfloat16 g_Wl[3*D_MODEL*D_MODEL];

#define LOG2_10K 13.287712379549449f

// ===========================================================================
// helpers
// ===========================================================================
__device__ __forceinline__ uint32_t smem_u32(const void* p) {
    uint32_t a;
    asm("{ .reg .u64 t; cvta.to.shared.u64 t, %1; cvt.u32.u64 %0, t; }"
        : "=r"(a) : "l"(p));
    return a;
}
__device__ __forceinline__ void ldsm_x4(uint32_t* r, uint32_t addr) {
    asm volatile("ldmatrix.sync.aligned.m8n8.x4.shared.b16 {%0,%1,%2,%3}, [%4];"
        : "=r"(r[0]), "=r"(r[1]), "=r"(r[2]), "=r"(r[3]) : "r"(addr));
}
__device__ __forceinline__ void ldsm_x4t(uint32_t* r, uint32_t addr) {
    asm volatile("ldmatrix.sync.aligned.m8n8.x4.trans.shared.b16 {%0,%1,%2,%3}, [%4];"
        : "=r"(r[0]), "=r"(r[1]), "=r"(r[2]), "=r"(r[3]) : "r"(addr));
}
__device__ __forceinline__ void mma16816(float* c, const uint32_t* a, const uint32_t* b) {
    asm volatile("mma.sync.aligned.m16n8k16.row.col.f32.bf16.bf16.f32 "
        "{%0,%1,%2,%3}, {%4,%5,%6,%7}, {%8,%9}, {%0,%1,%2,%3};"
        : "+f"(c[0]), "+f"(c[1]), "+f"(c[2]), "+f"(c[3])
        : "r"(a[0]), "r"(a[1]), "r"(a[2]), "r"(a[3]), "r"(b[0]), "r"(b[1]));
}
__device__ __forceinline__ void cp16(uint32_t saddr, const void* g) {
    asm volatile("cp.async.cg.shared.global [%0], [%1], 16;" :: "r"(saddr), "l"(g));
}
#define CP_COMMIT() asm volatile("cp.async.commit_group;" ::: "memory")
#define CP_WAIT0()  asm volatile("cp.async.wait_group 0;" ::: "memory")
#define CP_WAIT1()  asm volatile("cp.async.wait_group 1;" ::: "memory")

union BF2U { __nv_bfloat162 b2; unsigned u; };
__device__ __forceinline__ unsigned packbf(float x, float y) {
    BF2U u; u.b2 = __floats2bfloat162_rn(x, y); return u.u;
}
__device__ __forceinline__ float2 unpackbf(unsigned v) {
    BF2U u; u.u = v;
    return make_float2(__bfloat162float(u.b2.x), __bfloat162float(u.b2.y));
}
__device__ __forceinline__ void split4(float4 v, uint2& hi, uint2& lo) {
    BF2U h0, h1, l0, l1;
    h0.b2 = __floats2bfloat162_rn(v.x, v.y);
    h1.b2 = __floats2bfloat162_rn(v.z, v.w);
    l0.b2 = __floats2bfloat162_rn(v.x - __bfloat162float(h0.b2.x),
                                  v.y - __bfloat162float(h0.b2.y));
    l1.b2 = __floats2bfloat162_rn(v.z - __bfloat162float(h1.b2.x),
                                  v.w - __bfloat162float(h1.b2.y));
    hi = make_uint2(h0.u, h1.u);
    lo = make_uint2(l0.u, l1.u);
}

// ===========================================================================
// Split kernels
// ===========================================================================
__global__ __launch_bounds__(256) void dsplit_kernel(const float* __restrict__ src) {
    int idx = blockIdx.x * 256 + threadIdx.x;
    float4 v = *(const float4*)(src + (size_t)idx * 4);
    uint2 hi, lo;
    split4(v, hi, lo);
    *(uint2*)(g_Dh + (size_t)idx * 4) = hi;
    *(uint2*)(g_Dl + (size_t)idx * 4) = lo;
}

__global__ __launch_bounds__(256) void wsplit_kernel(
    const float* __restrict__ Wq, const float* __restrict__ Wk,
    const float* __restrict__ Wv)
{
    __shared__ __nv_bfloat16 th[32][40];
    __shared__ __nv_bfloat16 tl[32][40];
    const int mat = blockIdx.z;
    const float* __restrict__ W = (mat == 0) ? Wq : ((mat == 1) ? Wk : Wv);
    const int tid = threadIdx.x;
    const int k0 = blockIdx.x * 32;
    const int n0 = blockIdx.y * 32;
    {
        int r = tid >> 3, c4 = (tid & 7) * 4;
        float4 v = *(const float4*)(W + (size_t)(k0 + r) * D_MODEL + n0 + c4);
        uint2 hi, lo;
        split4(v, hi, lo);
        *(uint2*)&th[r][c4] = hi;
        *(uint2*)&tl[r][c4] = lo;
    }
    __syncthreads();
    {
        int r = tid >> 3, c4 = (tid & 7) * 4;
        __nv_bfloat16 hh[4], ll[4];
        #pragma unroll
        for (int j = 0; j < 4; ++j) { hh[j] = th[c4 + j][r]; ll[j] = tl[c4 + j][r]; }
        size_t o = ((size_t)mat << 20) + (size_t)(n0 + r) * D_MODEL + k0 + c4;
        *(uint2*)(g_Wh + o) = *(uint2*)hh;
        *(uint2*)(g_Wl + o) = *(uint2*)ll;
    }
}

// ===========================================================================
// QKV GEMM: bf16 HMMA hi/lo 3-pass, 128x128 tile, BK=32, cp.async dbl-buffer.
// ===========================================================================
#define ASTR 40
#define QT_BYTES (128 * ASTR * 2)      // 10240 per tile
#define QBUF_BYTES (4 * QT_BYTES)      // AH, AL, BH, BL
#define QKV_SMEM (2 * QBUF_BYTES)      // 81920

__global__ __launch_bounds__(256) void qkv_mma_kernel(
    const float* __restrict__ temporal,
    const float* __restrict__ bq, const float* __restrict__ bk,
    const float* __restrict__ bv)
{
    extern __shared__ char qsm[];
    const uint32_t base = smem_u32(qsm);

    const int mat = blockIdx.z;
    const float* __restrict__ bias = (mat == 0) ? bq : ((mat == 1) ? bk : bv);
    __nv_bfloat16* __restrict__ outH = (mat == 0) ? g_Qh : ((mat == 1) ? g_Kh : g_Vh);
    __nv_bfloat16* __restrict__ outL = (mat == 0) ? g_Ql : ((mat == 1) ? g_Kl : g_Vl);
    const __nv_bfloat16* __restrict__ Wh = g_Wh + ((size_t)mat << 20);
    const __nv_bfloat16* __restrict__ Wl = g_Wl + ((size_t)mat << 20);

    const int tid = threadIdx.x;
    const int lane = tid & 31;
    const int wid = tid >> 5;
    const int wm = wid & 1;
    const int wn = wid >> 1;
    const int m0 = blockIdx.x * 128;
    const int n0 = blockIdx.y * 128;

    const int lrow = tid >> 2;
    const int lc8  = (tid & 3) * 8;

    auto prefetch = [&](int kk, int buf) {
        uint32_t bb = base + buf * QBUF_BYTES;
        #pragma unroll
        for (int it = 0; it < 2; ++it) {
            int row = lrow + it * 64;
            uint32_t so = (uint32_t)(row * ASTR + lc8) * 2;
            size_t ga = (size_t)(m0 + row) * D_MODEL + kk + lc8;
            size_t gb = (size_t)(n0 + row) * D_MODEL + kk + lc8;
            cp16(bb + so,                 g_Dh + ga);
            cp16(bb + QT_BYTES + so,      g_Dl + ga);
            cp16(bb + 2 * QT_BYTES + so,  Wh + gb);
            cp16(bb + 3 * QT_BYTES + so,  Wl + gb);
        }
    };

    float acc[4][4][4];
    #pragma unroll
    for (int i = 0; i < 4; ++i)
        #pragma unroll
        for (int j = 0; j < 4; ++j)
            #pragma unroll
            for (int e = 0; e < 4; ++e) acc[i][j][e] = 0.0f;

    prefetch(0, 0);
    CP_COMMIT();

    for (int c = 0; c < 32; ++c) {
        __syncthreads();
        if (c + 1 < 32) {
            prefetch((c + 1) * 32, (c + 1) & 1);
            CP_COMMIT();
            CP_WAIT1();
        } else {
            CP_WAIT0();
        }
        __syncthreads();

        const uint32_t bb = base + (c & 1) * QBUF_BYTES;
        const uint32_t bAh = bb;
        const uint32_t bAl = bb + QT_BYTES;
        const uint32_t bBh = bb + 2 * QT_BYTES;
        const uint32_t bBl = bb + 3 * QT_BYTES;

        #pragma unroll
        for (int ks = 0; ks < 2; ++ks) {
            const int ko = ks * 16;
            uint32_t Ah[4][4], Al[4][4], Bh[2][4], Bl[2][4];
            const uint32_t aoff = (uint32_t)((wm * 64 + (lane & 15)) * ASTR
                                             + ko + ((lane >> 4) << 3)) * 2;
            #pragma unroll
            for (int ma = 0; ma < 4; ++ma) {
                ldsm_x4(Ah[ma], bAh + aoff + ma * 16 * ASTR * 2);
                ldsm_x4(Al[ma], bAl + aoff + ma * 16 * ASTR * 2);
            }
            {
                const int m = lane >> 3;
                #pragma unroll
                for (int nbp = 0; nbp < 2; ++nbp) {
                    int rr = wn * 32 + nbp * 16 + ((m >> 1) << 3) + (lane & 7);
                    int cc = ko + ((m & 1) << 3);
                    uint32_t off = (uint32_t)(rr * ASTR + cc) * 2;
                    ldsm_x4(Bh[nbp], bBh + off);
                    ldsm_x4(Bl[nbp], bBl + off);
                }
            }
            #pragma unroll
            for (int ma = 0; ma < 4; ++ma)
                #pragma unroll
                for (int nbp = 0; nbp < 2; ++nbp) {
                    mma16816(acc[ma][2*nbp+0], Ah[ma], Bh[nbp] + 0);
                    mma16816(acc[ma][2*nbp+0], Al[ma], Bh[nbp] + 0);
                    mma16816(acc[ma][2*nbp+0], Ah[ma], Bl[nbp] + 0);
                    mma16816(acc[ma][2*nbp+1], Ah[ma], Bh[nbp] + 2);
                    mma16816(acc[ma][2*nbp+1], Al[ma], Bh[nbp] + 2);
                    mma16816(acc[ma][2*nbp+1], Ah[ma], Bl[nbp] + 2);
                }
        }
    }

    // Epilogue: bias + RoPE, split to bf16 hi/lo, store [B,H,L,S]
    #pragma unroll
    for (int ma = 0; ma < 4; ++ma) {
        const int r0 = m0 + wm * 64 + ma * 16 + (lane >> 2);
        #pragma unroll
        for (int rg = 0; rg < 2; ++rg) {
            const int r = r0 + rg * 8;
            const int bb = r >> 11;
            const int ll = r & (SEQ - 1);
            float t = 0.0f;
            if (mat < 2) t = temporal[r];
            #pragma unroll
            for (int nb = 0; nb < 4; ++nb) {
                const int n = n0 + wn * 32 + nb * 8 + (lane & 3) * 2;
                const int hh = n >> 6;
                const int s = n & 63;
                float x0 = acc[ma][nb][rg * 2 + 0] + bias[n];
                float x1 = acc[ma][nb][rg * 2 + 1] + bias[n + 1];
                float2 v;
                if (mat < 2) {
                    float f = exp2f(-(float)s * (LOG2_10K / (float)HEAD_DIM));
                    float sn, cs;
                    sincosf(t * f, &sn, &cs);
                    v.x = x0 * cs - x1 * sn;
                    v.y = x1 * cs + x0 * sn;
                } else {
                    v.x = x0; v.y = x1;
                }
                unsigned uh = packbf(v.x, v.y);
                float2 hv = unpackbf(uh);
                unsigned ul = packbf(v.x - hv.x, v.y - hv.y);
                size_t o = (((size_t)(bb * NHEAD + hh)) * SEQ + ll) * HEAD_DIM + s;
                *(unsigned*)(outH + o) = uh;
                *(unsigned*)(outL + o) = ul;
            }
        }
    }
}

// ===========================================================================
// Flash attention: bf16 HMMA hi/lo. Q block 64 rows, 4 warps (128 thr),
// single-buffered K/V -> 90 KB smem -> 2 CTAs/SM for cross-CTA overlap.
// ===========================================================================
#define FSTR 72
#define KT_BYTES (128 * FSTR * 2)      // 18432 (K/V tiles, 128 rows)
#define QT2_BYTES (64 * FSTR * 2)      // 9216  (Q tile, 64 rows)
#define O_QH 0
#define O_QL QT2_BYTES
#define O_KV (2 * QT2_BYTES)
#define AT_SMEM (2 * QT2_BYTES + 4 * KT_BYTES)   // 92160

__global__ __launch_bounds__(128, 2) void attn_mma_kernel(
    const float* __restrict__ mask, float* __restrict__ out)
{
    extern __shared__ char smc[];
    const uint32_t base = smem_u32(smc);

    const int tid = threadIdx.x;
    const int lane = tid & 31;
    const int wid = tid >> 5;          // 0..3
    const int q0 = blockIdx.x * 64;
    const int hh = blockIdx.y;
    const int bb = blockIdx.z;

    const size_t hb = ((size_t)(bb * NHEAD + hh)) * SEQ * HEAD_DIM;

    // Q prefetch: 64 rows x 64 cols hi/lo (512 chunks of 16B, 128 threads)
    {
        #pragma unroll
        for (int it = 0; it < 4; ++it) {
            int idx = tid + it * 128;
            int row = idx >> 3;
            int c8  = (idx & 7) * 8;
            uint32_t so = (uint32_t)(row * FSTR + c8) * 2;
            size_t g = hb + (size_t)(q0 + row) * HEAD_DIM + c8;
            cp16(base + O_QH + so, g_Qh + g);
            cp16(base + O_QL + so, g_Ql + g);
        }
    }

    const uint32_t bKH = base + O_KV;
    const uint32_t bKL = bKH + KT_BYTES;
    const uint32_t bVH = bKL + KT_BYTES;
    const uint32_t bVL = bVH + KT_BYTES;

    float O[8][4];
    #pragma unroll
    for (int i = 0; i < 8; ++i)
        #pragma unroll
        for (int e = 0; e < 4; ++e) O[i][e] = 0.0f;
    float mrow[2] = {-INFINITY, -INFINITY};
    float lrow_[2] = {0.0f, 0.0f};

    const int r0 = lane >> 2;
    const int qr0 = q0 + wid * 16 + r0;
    const int cq = (lane & 3) * 2;
    const int m = lane >> 3;

    const int NIT = SEQ / 128;
    for (int c = 0; c < NIT; ++c) {
        __syncthreads();   // previous iteration done with KV buffer
        // KV load: 128 rows x 64 cols x 4 comps (4096 chunks / 128 thr = 32)
        {
            #pragma unroll
            for (int it = 0; it < 8; ++it) {
                int idx = tid + it * 128;
                int row = idx >> 3;
                int c8  = (idx & 7) * 8;
                uint32_t so = (uint32_t)(row * FSTR + c8) * 2;
                size_t g = hb + (size_t)(c * 128 + row) * HEAD_DIM + c8;
                cp16(bKH + so, g_Kh + g);
                cp16(bKL + so, g_Kl + g);
                cp16(bVH + so, g_Vh + g);
                cp16(bVL + so, g_Vl + g);
            }
        }
        CP_COMMIT();
        CP_WAIT0();
        __syncthreads();

        const int k0 = c * 128;

        // --- S = Q.K^T (3-pass), warp strip m16 x n128 ---
        float acc[16][4];
        #pragma unroll
        for (int i = 0; i < 16; ++i)
            #pragma unroll
            for (int e = 0; e < 4; ++e) acc[i][e] = 0.0f;

        #pragma unroll
        for (int ks = 0; ks < 4; ++ks) {
            uint32_t Ah[4], Al[4];
            const uint32_t aoff = (uint32_t)((wid * 16 + (lane & 15)) * FSTR
                                             + ks * 16 + ((lane >> 4) << 3)) * 2;
            ldsm_x4(Ah, base + O_QH + aoff);
            ldsm_x4(Al, base + O_QL + aoff);
            #pragma unroll
            for (int nbp = 0; nbp < 8; ++nbp) {
                uint32_t Bh[4], Bl[4];
                int rr = nbp * 16 + ((m >> 1) << 3) + (lane & 7);
                int cc = ks * 16 + ((m & 1) << 3);
                uint32_t off = (uint32_t)(rr * FSTR + cc) * 2;
                ldsm_x4(Bh, bKH + off);
                ldsm_x4(Bl, bKL + off);
                mma16816(acc[2*nbp+0], Ah, Bh + 0);
                mma16816(acc[2*nbp+0], Al, Bh + 0);
                mma16816(acc[2*nbp+0], Ah, Bl + 0);
                mma16816(acc[2*nbp+1], Ah, Bh + 2);
                mma16816(acc[2*nbp+1], Al, Bh + 2);
                mma16816(acc[2*nbp+1], Ah, Bl + 2);
            }
        }

        // --- online softmax (warp-local, quad shuffles) ---
        #pragma unroll
        for (int rg = 0; rg < 2; ++rg) {
            const float* mp = mask + (size_t)(qr0 + rg * 8) * SEQ + k0;
            float tm = -INFINITY;
            #pragma unroll
            for (int nb = 0; nb < 16; ++nb) {
                float2 mv = *(const float2*)(mp + nb * 8 + cq);
                float x0 = acc[nb][rg * 2 + 0] * 0.125f + mv.x;
                float x1 = acc[nb][rg * 2 + 1] * 0.125f + mv.y;
                acc[nb][rg * 2 + 0] = x0;
                acc[nb][rg * 2 + 1] = x1;
                tm = fmaxf(tm, fmaxf(x0, x1));
            }
            tm = fmaxf(tm, __shfl_xor_sync(0xffffffffu, tm, 1));
            tm = fmaxf(tm, __shfl_xor_sync(0xffffffffu, tm, 2));
            float mn = fmaxf(mrow[rg], tm);
            float corr = __expf(mrow[rg] - mn);
            float rs = 0.0f;
            #pragma unroll
            for (int nb = 0; nb < 16; ++nb) {
                float p0 = __expf(acc[nb][rg * 2 + 0] - mn);
                float p1 = __expf(acc[nb][rg * 2 + 1] - mn);
                acc[nb][rg * 2 + 0] = p0;
                acc[nb][rg * 2 + 1] = p1;
                rs += p0 + p1;
            }
            rs += __shfl_xor_sync(0xffffffffu, rs, 1);
            rs += __shfl_xor_sync(0xffffffffu, rs, 2);
            lrow_[rg] = lrow_[rg] * corr + rs;
            mrow[rg] = mn;
            #pragma unroll
            for (int nb = 0; nb < 8; ++nb) {
                O[nb][rg * 2 + 0] *= corr;
                O[nb][rg * 2 + 1] *= corr;
            }
        }

        // --- O += P.V (3-pass), P re-packed from registers ---
        #pragma unroll
        for (int ks = 0; ks < 8; ++ks) {
            uint32_t ph[4], pl[4];
            #pragma unroll
            for (int half = 0; half < 2; ++half) {
                const float* a0 = acc[2 * ks + half];
                unsigned h01 = packbf(a0[0], a0[1]);
                unsigned h23 = packbf(a0[2], a0[3]);
                float2 f01 = unpackbf(h01);
                float2 f23 = unpackbf(h23);
                unsigned l01 = packbf(a0[0] - f01.x, a0[1] - f01.y);
                unsigned l23 = packbf(a0[2] - f23.x, a0[3] - f23.y);
                ph[half * 2 + 0] = h01; ph[half * 2 + 1] = h23;
                pl[half * 2 + 0] = l01; pl[half * 2 + 1] = l23;
            }
            #pragma unroll
            for (int nbp = 0; nbp < 4; ++nbp) {
                uint32_t Vh[4], Vl[4];
                int rr = ks * 16 + ((m & 1) << 3) + (lane & 7);
                int cc = nbp * 16 + ((m >> 1) << 3);
                uint32_t off = (uint32_t)(rr * FSTR + cc) * 2;
                ldsm_x4t(Vh, bVH + off);
                ldsm_x4t(Vl, bVL + off);
                mma16816(O[2*nbp+0], ph, Vh + 0);
                mma16816(O[2*nbp+0], pl, Vh + 0);
                mma16816(O[2*nbp+0], ph, Vl + 0);
                mma16816(O[2*nbp+1], ph, Vh + 2);
                mma16816(O[2*nbp+1], pl, Vh + 2);
                mma16816(O[2*nbp+1], ph, Vl + 2);
            }
        }
    }

    // Epilogue
    float inv0 = 1.0f / lrow_[0];
    float inv1 = 1.0f / lrow_[1];
    #pragma unroll
    for (int rg = 0; rg < 2; ++rg) {
        float inv = rg ? inv1 : inv0;
        size_t ob = (size_t)(bb * SEQ + qr0 + rg * 8) * D_MODEL + hh * HEAD_DIM;
        #pragma unroll
        for (int nb = 0; nb < 8; ++nb) {
            float2 v = make_float2(O[nb][rg * 2 + 0] * inv, O[nb][rg * 2 + 1] * inv);
            *(float2*)(out + ob + nb * 8 + cq) = v;
        }
    }
}

// ---------------------------------------------------------------------------
// Launch. inputs: 0=data 1=temporal 2=mask 3=Wq 4=bq 5=Wk 6=bk 7=Wv 8=bv
// ---------------------------------------------------------------------------
extern "C" void kernel_launch(void* const* d_in, const int* in_sizes, int n_in,
                              void* d_out, int out_size)
{
    const float* data     = (const float*)d_in[0];
    const float* temporal = (const float*)d_in[1];
    const float* mask     = (const float*)d_in[2];
    const float* Wq = (const float*)d_in[3];
    const float* bq = (const float*)d_in[4];
    const float* Wk = (const float*)d_in[5];
    const float* bk = (const float*)d_in[6];
    const float* Wv = (const float*)d_in[7];
    const float* bv = (const float*)d_in[8];
    float* out = (float*)d_out;

    cudaFuncSetAttribute(qkv_mma_kernel,
                         cudaFuncAttributeMaxDynamicSharedMemorySize, QKV_SMEM);
    cudaFuncSetAttribute(attn_mma_kernel,
                         cudaFuncAttributeMaxDynamicSharedMemorySize, AT_SMEM);

    dsplit_kernel<<<(M_TOT * D_MODEL / 4) / 256, 256>>>(data);
    dim3 gw(D_MODEL / 32, D_MODEL / 32, 3);
    wsplit_kernel<<<gw, 256>>>(Wq, Wk, Wv);

    dim3 g1(M_TOT / 128, D_MODEL / 128, 3);
    qkv_mma_kernel<<<g1, 256, QKV_SMEM>>>(temporal, bq, bk, bv);

    dim3 g2(SEQ / 64, NHEAD, BATCH);
    attn_mma_kernel<<<g2, 128, AT_SMEM>>>(mask, out);
}